// round 2
// baseline (speedup 1.0000x reference)
#include <cuda_runtime.h>

// Problem constants
#define HD      768
#define SEQ     256
#define BATCH   4
#define ROWS    (BATCH * SEQ)      // 1024
#define NTOT    (3 * HD)           // 2304 : [h | ha | hb]
#define NP      54
#define THRESH  0.5f
#define OUT_ELEMS (BATCH * SEQ * SEQ * NP)   // 14,155,776

// Scratch (device globals — no allocation allowed)
__device__ float g_hab[ROWS * NTOT];          // 9.44 MB
__device__ int   g_cand[ROWS];
__device__ int   g_pairs[BATCH * SEQ * SEQ];  // worst case 262144
__device__ int   g_cnt;

// ---------------------------------------------------------------------------
// Kernel 1: zero output + reset pair counter
// ---------------------------------------------------------------------------
__global__ void zero_kernel(float4* __restrict__ out) {
    int idx = blockIdx.x * blockDim.x + threadIdx.x;   // exactly OUT_ELEMS/4 threads
    out[idx] = make_float4(0.f, 0.f, 0.f, 0.f);
    if (idx == 0) g_cnt = 0;
}

// ---------------------------------------------------------------------------
// Kernel 2: fused SGEMM  C[1024, 2304] where
//   n in [0,768)     : relu( x @ W1s^T + b1s )      (h)
//   n in [768,1536)  : x @ Wp1[:, :H]^T             (ha)
//   n in [1536,2304) : x @ Wp1[:, H:]^T             (hb)
// A = x [1024,768] row-major, all weights K-contiguous.
// 128x128 tile, BK=16, 256 threads, 8x8 per thread.
// ---------------------------------------------------------------------------
#define BM 128
#define BN 128
#define BK 16
#define PAD 4

__global__ void __launch_bounds__(256, 1) gemm_kernel(
    const float* __restrict__ X,
    const float* __restrict__ W1s,
    const float* __restrict__ b1s,
    const float* __restrict__ Wp1)
{
    __shared__ float As[BK][BM + PAD];
    __shared__ float Bs[BK][BN + PAD];

    const int tid = threadIdx.x;
    const int n0 = blockIdx.x * BN;    // 0..17 * 128
    const int m0 = blockIdx.y * BM;    // 0..7  * 128

    // Select weight region (tiles never straddle 768-boundaries: 768 % 128 == 0)
    const float* Wsrc;
    int rowstride, coloff, nbase;
    bool do_relu;
    if (n0 < HD)            { Wsrc = W1s; rowstride = HD;     coloff = 0;  nbase = 0;      do_relu = true;  }
    else if (n0 < 2 * HD)   { Wsrc = Wp1; rowstride = 2 * HD; coloff = 0;  nbase = HD;     do_relu = false; }
    else                    { Wsrc = Wp1; rowstride = 2 * HD; coloff = HD; nbase = 2 * HD; do_relu = false; }

    float acc[8][8];
    #pragma unroll
    for (int i = 0; i < 8; i++)
        #pragma unroll
        for (int j = 0; j < 8; j++) acc[i][j] = 0.f;

    // load mapping: 512 float4 per tile, 2 per thread
    const int lm0 = tid >> 2;          // 0..63   (first element row)
    const int lkq = (tid & 3) * 4;     // k offset 0,4,8,12

    const int ty = tid >> 4;           // 0..15
    const int tx = tid & 15;           // 0..15

    for (int k0 = 0; k0 < HD; k0 += BK) {
        // --- load A tile (rows m0+lm0, m0+lm0+64), k0+lkq..+3, transpose into As[k][m]
        #pragma unroll
        for (int half = 0; half < 2; half++) {
            int m = lm0 + half * 64;
            float4 v = *(const float4*)&X[(m0 + m) * HD + k0 + lkq];
            As[lkq + 0][m] = v.x;
            As[lkq + 1][m] = v.y;
            As[lkq + 2][m] = v.z;
            As[lkq + 3][m] = v.w;
        }
        // --- load B tile: n0+lm0(+64), weight row r = n - nbase
        #pragma unroll
        for (int half = 0; half < 2; half++) {
            int n = lm0 + half * 64;
            int r = n0 + n - nbase;
            float4 v = *(const float4*)&Wsrc[r * rowstride + coloff + k0 + lkq];
            Bs[lkq + 0][n] = v.x;
            Bs[lkq + 1][n] = v.y;
            Bs[lkq + 2][n] = v.z;
            Bs[lkq + 3][n] = v.w;
        }
        __syncthreads();

        #pragma unroll
        for (int k = 0; k < BK; k++) {
            float a[8], b[8];
            float4 a0 = *(const float4*)&As[k][ty * 8];
            float4 a1 = *(const float4*)&As[k][ty * 8 + 4];
            float4 b0 = *(const float4*)&Bs[k][tx * 8];
            float4 b1 = *(const float4*)&Bs[k][tx * 8 + 4];
            a[0]=a0.x; a[1]=a0.y; a[2]=a0.z; a[3]=a0.w;
            a[4]=a1.x; a[5]=a1.y; a[6]=a1.z; a[7]=a1.w;
            b[0]=b0.x; b[1]=b0.y; b[2]=b0.z; b[3]=b0.w;
            b[4]=b1.x; b[5]=b1.y; b[6]=b1.z; b[7]=b1.w;
            #pragma unroll
            for (int i = 0; i < 8; i++)
                #pragma unroll
                for (int j = 0; j < 8; j++)
                    acc[i][j] = fmaf(a[i], b[j], acc[i][j]);
        }
        __syncthreads();
    }

    // epilogue
    #pragma unroll
    for (int i = 0; i < 8; i++) {
        int m = m0 + ty * 8 + i;
        #pragma unroll
        for (int j = 0; j < 8; j++) {
            int n = n0 + tx * 8 + j;
            float v = acc[i][j];
            if (do_relu) v = fmaxf(v + b1s[n], 0.f);
            g_hab[m * NTOT + n] = v;
        }
    }
}

// ---------------------------------------------------------------------------
// Kernel 3: cand[row] = (h[row] . W2s[0] + b2s[0]) > THRESH
// ---------------------------------------------------------------------------
__global__ void cand_kernel(const float* __restrict__ W2s,
                            const float* __restrict__ b2s)
{
    __shared__ float red[256];
    int row = blockIdx.x;
    int t = threadIdx.x;
    float s = 0.f;
    #pragma unroll
    for (int k = t; k < HD; k += 256)
        s += g_hab[row * NTOT + k] * W2s[k];
    red[t] = s;
    __syncthreads();
    for (int off = 128; off > 0; off >>= 1) {
        if (t < off) red[t] += red[t + off];
        __syncthreads();
    }
    if (t == 0) g_cand[row] = (red[0] + b2s[0]) > THRESH ? 1 : 0;
}

// ---------------------------------------------------------------------------
// Kernel 4: compact valid (b,i,j) pairs
// ---------------------------------------------------------------------------
__global__ void compact_kernel() {
    int t = blockIdx.x * blockDim.x + threadIdx.x;   // 262144 threads
    int b = t >> 16;
    int i = (t >> 8) & 255;
    int j = t & 255;
    if (i != j && g_cand[b * SEQ + i] && g_cand[b * SEQ + j]) {
        int pos = atomicAdd(&g_cnt, 1);
        g_pairs[pos] = t;                            // t encodes (b,i,j)
    }
}

// ---------------------------------------------------------------------------
// Kernel 5: per valid pair, out[b,i,j,:] = relu(ha_i + hb_j + bp1) @ Wp2^T + bp2
// grid-stride over pairs; 128 threads/block
// ---------------------------------------------------------------------------
__global__ void pair_kernel(const float* __restrict__ bp1,
                            const float* __restrict__ Wp2,
                            const float* __restrict__ bp2,
                            float* __restrict__ out)
{
    __shared__ float v[HD];
    const int cnt = g_cnt;
    const int warp = threadIdx.x >> 5;
    const int lane = threadIdx.x & 31;

    for (int p = blockIdx.x; p < cnt; p += gridDim.x) {
        int code = g_pairs[p];
        int b = code >> 16;
        int i = (code >> 8) & 255;
        int j = code & 255;
        int rowi = b * SEQ + i;
        int rowj = b * SEQ + j;

        for (int h = threadIdx.x; h < HD; h += blockDim.x)
            v[h] = fmaxf(g_hab[rowi * NTOT + HD + h] +
                         g_hab[rowj * NTOT + 2 * HD + h] + bp1[h], 0.f);
        __syncthreads();

        for (int pp = warp; pp < NP; pp += (blockDim.x >> 5)) {
            float s = 0.f;
            for (int h = lane; h < HD; h += 32)
                s += v[h] * Wp2[pp * HD + h];
            #pragma unroll
            for (int o = 16; o > 0; o >>= 1)
                s += __shfl_xor_sync(0xffffffffu, s, o);
            if (lane == 0)
                out[(rowi * SEQ + j) * NP + pp] = s + bp2[pp];
        }
        __syncthreads();
    }
}

// ---------------------------------------------------------------------------
extern "C" void kernel_launch(void* const* d_in, const int* in_sizes, int n_in,
                              void* d_out, int out_size)
{
    const float* x   = (const float*)d_in[0];   // [4,256,768]
    const float* W1s = (const float*)d_in[1];   // [768,768]
    const float* b1s = (const float*)d_in[2];   // [768]
    const float* W2s = (const float*)d_in[3];   // [2,768]
    const float* b2s = (const float*)d_in[4];   // [2]
    const float* Wp1 = (const float*)d_in[5];   // [768,1536]
    const float* bp1 = (const float*)d_in[6];   // [768]
    const float* Wp2 = (const float*)d_in[7];   // [54,768]
    const float* bp2 = (const float*)d_in[8];   // [54]
    float* out = (float*)d_out;

    // 1) zero output (56.6 MB) + reset counter
    zero_kernel<<<OUT_ELEMS / 4 / 256, 256>>>((float4*)out);

    // 2) fused SGEMM: h | ha | hb
    dim3 ggrid(NTOT / BN, ROWS / BM);            // (18, 8)
    gemm_kernel<<<ggrid, 256>>>(x, W1s, b1s, Wp1);

    // 3) candidate mask
    cand_kernel<<<ROWS, 256>>>(W2s, b2s);

    // 4) compact valid pairs
    compact_kernel<<<(BATCH * SEQ * SEQ) / 256, 256>>>();

    // 5) sparse pair logits
    pair_kernel<<<256, 128>>>(bp1, Wp2, bp2, out);
}